// round 10
// baseline (speedup 1.0000x reference)
#include <cuda_runtime.h>

// Problem constants (fixed by the dataset)
#define NN 100000
#define EE 1600000

// Scratch: __device__ globals only, referenced ONLY from device code
// (host-side symbol use binds the ATS-dereferenceable host shadow -> R2 bug).
__device__ int   g_is64;
__device__ int   g_deg[NN];      // per-node in-degree (histogram)
__device__ int   g_off[NN];      // exclusive prefix = CSR row start
__device__ int   g_cur[NN];      // scatter cursor
__device__ int   g_csr[EE];      // src indices grouped by dst
__device__ int   g_bsum[1024];   // scan block sums
__device__ int   g_boff[1024];   // scan block offsets
__device__ float g_t1[NN * 32];
__device__ float g_a1[NN * 32];  // layer-1 root part (init by node1)
__device__ float g_t2[NN * 48];
__device__ float g_a2[NN * 48];  // layer-2 root part (init by fused2)
__device__ float g_t3[NN * 16];

// Packed fp32x2 helpers (Blackwell FFMA2 — exact fp32, 2 FMAs/inst)
__device__ __forceinline__ unsigned long long fma2(
    unsigned long long a, unsigned long long b, unsigned long long c) {
    unsigned long long d;
    asm("fma.rn.f32x2 %0, %1, %2, %3;" : "=l"(d) : "l"(a), "l"(b), "l"(c));
    return d;
}
__device__ __forceinline__ unsigned long long add2(
    unsigned long long a, unsigned long long b) {
    unsigned long long d;
    asm("add.rn.f32x2 %0, %1, %2;" : "=l"(d) : "l"(a), "l"(b));
    return d;
}
__device__ __forceinline__ unsigned long long bcast2(float v) {
    unsigned long long d;
    asm("mov.b64 %0, {%1, %1};" : "=l"(d) : "f"(v));
    return d;
}

// ---------------------------------------------------------------------------
// CSR build (runs on side stream, hidden behind node1)
// ---------------------------------------------------------------------------
__global__ __launch_bounds__(256) void k_init(const void* __restrict__ ei, int N) {
    int i = blockIdx.x * blockDim.x + threadIdx.x;
    if (i < N) g_deg[i] = 0;
    if (i == 0) {
        const long long* p = (const long long*)ei;
        int ok = 1;
        for (int q = 0; q < 64; q++) {
            long long v = p[q];
            if (v < 0 || v >= (long long)N) { ok = 0; break; }
        }
        g_is64 = ok;
    }
}

__global__ __launch_bounds__(256) void k_hist(const void* __restrict__ ei, int E) {
    int i = blockIdx.x * blockDim.x + threadIdx.x;
    if (i >= E) return;
    int d;
    if (g_is64) d = (int)((const long long*)ei)[E + i];
    else        d = ((const int*)ei)[E + i];
    atomicAdd(&g_deg[d], 1);
}

__global__ __launch_bounds__(256) void k_scanA(int N) {
    __shared__ int s[256];
    int b = blockIdx.x, t = threadIdx.x;
    int base = b * 1024 + t * 4;
    int sum = 0;
#pragma unroll
    for (int i = 0; i < 4; i++) {
        int idx = base + i;
        if (idx < N) sum += g_deg[idx];
    }
    s[t] = sum;
    __syncthreads();
#pragma unroll
    for (int d = 128; d > 0; d >>= 1) {
        if (t < d) s[t] += s[t + d];
        __syncthreads();
    }
    if (t == 0) g_bsum[b] = s[0];
}

__global__ __launch_bounds__(1024) void k_scanB(int NB) {
    __shared__ int s[1024];
    int t = threadIdx.x;
    int v = (t < NB) ? g_bsum[t] : 0;
    s[t] = v;
    __syncthreads();
    for (int d = 1; d < 1024; d <<= 1) {
        int x = (t >= d) ? s[t - d] : 0;
        __syncthreads();
        s[t] += x;
        __syncthreads();
    }
    if (t < NB) g_boff[t] = s[t] - v;   // exclusive
}

__global__ __launch_bounds__(256) void k_scanC(int N) {
    __shared__ int s[256];
    int b = blockIdx.x, t = threadIdx.x;
    int base = b * 1024 + t * 4;
    int v[4];
    int sum = 0;
#pragma unroll
    for (int i = 0; i < 4; i++) {
        int idx = base + i;
        v[i] = (idx < N) ? g_deg[idx] : 0;
        sum += v[i];
    }
    s[t] = sum;
    __syncthreads();
    for (int d = 1; d < 256; d <<= 1) {
        int x = (t >= d) ? s[t - d] : 0;
        __syncthreads();
        s[t] += x;
        __syncthreads();
    }
    int run = s[t] - sum + g_boff[b];
#pragma unroll
    for (int i = 0; i < 4; i++) {
        int idx = base + i;
        if (idx < N) {
            g_off[idx] = run;
            g_cur[idx] = run;
            run += v[i];
        }
    }
}

__global__ __launch_bounds__(256) void k_scatter(const void* __restrict__ ei, int E) {
    int i = blockIdx.x * blockDim.x + threadIdx.x;
    if (i >= E) return;
    int s, d;
    if (g_is64) {
        const long long* p = (const long long*)ei;
        s = (int)p[i];
        d = (int)p[E + i];
    } else {
        const int* p = (const int*)ei;
        s = p[i];
        d = p[E + i];
    }
    int pos = atomicAdd(&g_cur[d], 1);
    g_csr[pos] = s;
}

// ---------------------------------------------------------------------------
// Dual-GEMM j-tile body, FFMA2: 8 outputs as 4 packed f32x2 accums per matrix.
// ---------------------------------------------------------------------------
#define JTILE_BODY2(IN, OUT)                                                   \
    unsigned long long at2[4], ar2[4];                                         \
    {                                                                          \
        ulonglong2 binit0 = *(const ulonglong2*)&sb[jt];                       \
        ulonglong2 binit1 = *(const ulonglong2*)&sb[jt + 4];                   \
        at2[0] = 0ull; at2[1] = 0ull; at2[2] = 0ull; at2[3] = 0ull;            \
        ar2[0] = binit0.x; ar2[1] = binit0.y;                                  \
        ar2[2] = binit1.x; ar2[3] = binit1.y;                                  \
    }                                                                          \
    _Pragma("unroll")                                                          \
    for (int k = 0; k < IN; k++) {                                             \
        unsigned long long hk2 = bcast2(h[k]);                                 \
        ulonglong2 wr01 = *(const ulonglong2*)&sWr[k * OUT + jt];              \
        ulonglong2 wr23 = *(const ulonglong2*)&sWr[k * OUT + jt + 4];          \
        ulonglong2 wo01 = *(const ulonglong2*)&sWo[k * OUT + jt];              \
        ulonglong2 wo23 = *(const ulonglong2*)&sWo[k * OUT + jt + 4];          \
        at2[0] = fma2(hk2, wr01.x, at2[0]);                                    \
        at2[1] = fma2(hk2, wr01.y, at2[1]);                                    \
        at2[2] = fma2(hk2, wr23.x, at2[2]);                                    \
        at2[3] = fma2(hk2, wr23.y, at2[3]);                                    \
        ar2[0] = fma2(hk2, wo01.x, ar2[0]);                                    \
        ar2[1] = fma2(hk2, wo01.y, ar2[1]);                                    \
        ar2[2] = fma2(hk2, wo23.x, ar2[2]);                                    \
        ar2[3] = fma2(hk2, wo23.y, ar2[3]);                                    \
    }

// Neighbor-row aggregation into FH float4 accumulators (FH*4 floats wide).
// acc must be an array of FH float4, pre-initialized.
#define AGG_NEIGHBORS(TSRC, FH)                                                \
    {                                                                          \
        int beg = g_off[i];                                                    \
        int end = beg + g_deg[i];                                              \
        int j = beg;                                                           \
        for (; j + 1 < end; j += 2) {                                          \
            int s0 = g_csr[j], s1 = g_csr[j + 1];                              \
            const float4* r0 = (const float4*)(TSRC + (size_t)s0 * (FH * 4));  \
            const float4* r1 = (const float4*)(TSRC + (size_t)s1 * (FH * 4));  \
            _Pragma("unroll")                                                  \
            for (int q = 0; q < FH; q++) {                                     \
                float4 v0 = r0[q];                                             \
                float4 v1 = r1[q];                                             \
                acc[q].x += v0.x + v1.x;                                       \
                acc[q].y += v0.y + v1.y;                                       \
                acc[q].z += v0.z + v1.z;                                       \
                acc[q].w += v0.w + v1.w;                                       \
            }                                                                  \
        }                                                                      \
        if (j < end) {                                                         \
            const float4* r0 = (const float4*)(TSRC + (size_t)g_csr[j] * (FH * 4)); \
            _Pragma("unroll")                                                  \
            for (int q = 0; q < FH; q++) {                                     \
                float4 v0 = r0[q];                                             \
                acc[q].x += v0.x; acc[q].y += v0.y;                            \
                acc[q].z += v0.z; acc[q].w += v0.w;                            \
            }                                                                  \
        }                                                                      \
    }

// ---------------------------------------------------------------------------
// K1: layer 1 node kernel. h0 = concat(x[48], ax[16]) -> 64
//     t1 = h0 @ W1_rel ; a1 = h0 @ W1_root + b1
// ---------------------------------------------------------------------------
__global__ __launch_bounds__(256) void k_node1(
    const float* __restrict__ x, const float* __restrict__ ax,
    const float* __restrict__ Wrel, const float* __restrict__ Wroot,
    const float* __restrict__ b, int N)
{
    __shared__ __align__(16) float sWr[64 * 32];
    __shared__ __align__(16) float sWo[64 * 32];
    __shared__ __align__(16) float sb[32];
    for (int t = threadIdx.x; t < 64 * 32; t += 256) { sWr[t] = Wrel[t]; sWo[t] = Wroot[t]; }
    if (threadIdx.x < 32) sb[threadIdx.x] = b[threadIdx.x];
    __syncthreads();

    int i = blockIdx.x * 256 + threadIdx.x;
    if (i >= N) return;

    float h[64];
    const float4* xp = (const float4*)(x + (size_t)i * 48);
#pragma unroll
    for (int q = 0; q < 12; q++) {
        float4 v = xp[q];
        h[4*q] = v.x; h[4*q+1] = v.y; h[4*q+2] = v.z; h[4*q+3] = v.w;
    }
    const float4* ap = (const float4*)(ax + (size_t)i * 16);
#pragma unroll
    for (int q = 0; q < 4; q++) {
        float4 v = ap[q];
        h[48+4*q] = v.x; h[48+4*q+1] = v.y; h[48+4*q+2] = v.z; h[48+4*q+3] = v.w;
    }

    float* t1 = g_t1 + (size_t)i * 32;
    float* a1 = g_a1 + (size_t)i * 32;
#pragma unroll 1
    for (int jt = 0; jt < 32; jt += 8) {
        JTILE_BODY2(64, 32)
        *(ulonglong2*)&t1[jt]     = make_ulonglong2(at2[0], at2[1]);
        *(ulonglong2*)&t1[jt + 4] = make_ulonglong2(at2[2], at2[3]);
        *(ulonglong2*)&a1[jt]     = make_ulonglong2(ar2[0], ar2[1]);
        *(ulonglong2*)&a1[jt + 4] = make_ulonglong2(ar2[2], ar2[3]);
    }
}

// ---------------------------------------------------------------------------
// Fused layer 2: agg(t1) + a1 -> relu -> concat lf -> GEMM 48x48 dual
// ---------------------------------------------------------------------------
__global__ __launch_bounds__(256) void k_fused2(
    const float* __restrict__ lf,
    const float* __restrict__ Wrel, const float* __restrict__ Wroot,
    const float* __restrict__ b, int N)
{
    __shared__ __align__(16) float sWr[48 * 48];
    __shared__ __align__(16) float sWo[48 * 48];
    __shared__ __align__(16) float sb[48];
    for (int t = threadIdx.x; t < 48 * 48; t += 256) { sWr[t] = Wrel[t]; sWo[t] = Wroot[t]; }
    if (threadIdx.x < 48) sb[threadIdx.x] = b[threadIdx.x];
    __syncthreads();

    int i = blockIdx.x * 256 + threadIdx.x;
    if (i >= N) return;

    // init accumulators with root part a1[i], aggregate neighbor t1 rows
    float4 acc[8];
    const float4* a1p = (const float4*)(g_a1 + (size_t)i * 32);
#pragma unroll
    for (int q = 0; q < 8; q++) acc[q] = a1p[q];
    AGG_NEIGHBORS(g_t1, 8)

    float h[48];
#pragma unroll
    for (int q = 0; q < 8; q++) {
        h[4*q]   = fmaxf(acc[q].x, 0.0f);
        h[4*q+1] = fmaxf(acc[q].y, 0.0f);
        h[4*q+2] = fmaxf(acc[q].z, 0.0f);
        h[4*q+3] = fmaxf(acc[q].w, 0.0f);
    }
    const float4* lp = (const float4*)(lf + (size_t)i * 16);
#pragma unroll
    for (int q = 0; q < 4; q++) {
        float4 v = lp[q];
        h[32+4*q] = v.x; h[32+4*q+1] = v.y; h[32+4*q+2] = v.z; h[32+4*q+3] = v.w;
    }

    float* t2 = g_t2 + (size_t)i * 48;
    float* a2 = g_a2 + (size_t)i * 48;
#pragma unroll 1
    for (int jt = 0; jt < 48; jt += 8) {
        JTILE_BODY2(48, 48)
        *(ulonglong2*)&t2[jt]     = make_ulonglong2(at2[0], at2[1]);
        *(ulonglong2*)&t2[jt + 4] = make_ulonglong2(at2[2], at2[3]);
        *(ulonglong2*)&a2[jt]     = make_ulonglong2(ar2[0], ar2[1]);
        *(ulonglong2*)&a2[jt + 4] = make_ulonglong2(ar2[2], ar2[3]);
    }
}

// ---------------------------------------------------------------------------
// Fused layer 3: agg(t2) + a2 -> relu -> GEMM 48x16 dual
//     t3 = h2 @ W3_rel ; out_init = h2 @ W3_root + b3 + ax
// ---------------------------------------------------------------------------
__global__ __launch_bounds__(256) void k_fused3(
    const float* __restrict__ ax,
    const float* __restrict__ Wrel, const float* __restrict__ Wroot,
    const float* __restrict__ b, float* __restrict__ out, int N)
{
    __shared__ __align__(16) float sWr[48 * 16];
    __shared__ __align__(16) float sWo[48 * 16];
    __shared__ __align__(16) float sb[16];
    for (int t = threadIdx.x; t < 48 * 16; t += 256) { sWr[t] = Wrel[t]; sWo[t] = Wroot[t]; }
    if (threadIdx.x < 16) sb[threadIdx.x] = b[threadIdx.x];
    __syncthreads();

    int i = blockIdx.x * 256 + threadIdx.x;
    if (i >= N) return;

    float4 acc[12];
    const float4* a2p = (const float4*)(g_a2 + (size_t)i * 48);
#pragma unroll
    for (int q = 0; q < 12; q++) acc[q] = a2p[q];
    AGG_NEIGHBORS(g_t2, 12)

    float h[48];
#pragma unroll
    for (int q = 0; q < 12; q++) {
        h[4*q]   = fmaxf(acc[q].x, 0.0f);
        h[4*q+1] = fmaxf(acc[q].y, 0.0f);
        h[4*q+2] = fmaxf(acc[q].z, 0.0f);
        h[4*q+3] = fmaxf(acc[q].w, 0.0f);
    }

    const ulonglong2* axp = (const ulonglong2*)(ax + (size_t)i * 16);
    float* t3 = g_t3 + (size_t)i * 16;
    float* o  = out + (size_t)i * 16;
#pragma unroll 1
    for (int jt = 0; jt < 16; jt += 8) {
        JTILE_BODY2(48, 16)
        ulonglong2 av0 = axp[jt / 4];
        ulonglong2 av1 = axp[jt / 4 + 1];
        *(ulonglong2*)&t3[jt]     = make_ulonglong2(at2[0], at2[1]);
        *(ulonglong2*)&t3[jt + 4] = make_ulonglong2(at2[2], at2[3]);
        *(ulonglong2*)&o[jt]      = make_ulonglong2(add2(ar2[0], av0.x),
                                                    add2(ar2[1], av0.y));
        *(ulonglong2*)&o[jt + 4]  = make_ulonglong2(add2(ar2[2], av1.x),
                                                    add2(ar2[3], av1.y));
    }
}

// ---------------------------------------------------------------------------
// Final aggregation: out[i] += sum of neighbors' t3 rows (CH=4 lanes/node)
// ---------------------------------------------------------------------------
__global__ __launch_bounds__(256) void k_agg3(float* __restrict__ out, int N) {
    int tid = blockIdx.x * blockDim.x + threadIdx.x;
    if (tid >= N * 4) return;
    int n = tid >> 2;
    int c = tid & 3;

    int beg = g_off[n];
    int end = beg + g_deg[n];

    float4 a = make_float4(0.f, 0.f, 0.f, 0.f);
    float4 a2 = make_float4(0.f, 0.f, 0.f, 0.f);

    int j = beg;
    for (; j + 3 < end; j += 4) {
        int s0 = g_csr[j], s1 = g_csr[j+1], s2 = g_csr[j+2], s3 = g_csr[j+3];
        float4 v0 = *(const float4*)(g_t3 + (size_t)s0 * 16 + c*4);
        float4 v1 = *(const float4*)(g_t3 + (size_t)s1 * 16 + c*4);
        float4 v2 = *(const float4*)(g_t3 + (size_t)s2 * 16 + c*4);
        float4 v3 = *(const float4*)(g_t3 + (size_t)s3 * 16 + c*4);
        a.x += v0.x; a.y += v0.y; a.z += v0.z; a.w += v0.w;
        a2.x += v1.x; a2.y += v1.y; a2.z += v1.z; a2.w += v1.w;
        a.x += v2.x; a.y += v2.y; a.z += v2.z; a.w += v2.w;
        a2.x += v3.x; a2.y += v3.y; a2.z += v3.z; a2.w += v3.w;
    }
    for (; j < end; j++) {
        int s = g_csr[j];
        float4 v = *(const float4*)(g_t3 + (size_t)s * 16 + c*4);
        a.x += v.x; a.y += v.y; a.z += v.z; a.w += v.w;
    }

    float* ap = out + (size_t)n * 16 + c*4;
    float4 cur = *(float4*)ap;
    *(float4*)ap = make_float4(cur.x + a.x + a2.x, cur.y + a.y + a2.y,
                               cur.z + a.z + a2.z, cur.w + a.w + a2.w);
}

// ---------------------------------------------------------------------------
// kernel_launch: CSR build on side stream overlapped with k_node1, then the
// fused chain node1 -> fused2 -> fused3 -> agg3.
// ---------------------------------------------------------------------------
extern "C" void kernel_launch(void* const* d_in, const int* in_sizes, int n_in,
                              void* d_out, int out_size)
{
    const float* x   = (const float*)d_in[0];
    const void*  ei  = d_in[1];
    const float* ax  = (const float*)d_in[2];
    const float* lf  = (const float*)d_in[3];
    const float* W1r = (const float*)d_in[4];
    const float* b1  = (const float*)d_in[5];
    const float* W1o = (const float*)d_in[6];
    const float* W2r = (const float*)d_in[7];
    const float* b2  = (const float*)d_in[8];
    const float* W2o = (const float*)d_in[9];
    const float* W3r = (const float*)d_in[10];
    const float* b3  = (const float*)d_in[11];
    const float* W3o = (const float*)d_in[12];
    float* out = (float*)d_out;

    const int N = in_sizes[0] / 48;
    const int E = in_sizes[1] / 2;

    const int TB = 256;
    const int nodeBlocks = (N + TB - 1) / TB;
    const int edgeBlocks = (E + TB - 1) / TB;
    const int NB = (N + 1023) / 1024;   // scan blocks (98 for N=100k)

    static cudaStream_t s2 = nullptr;
    static cudaEvent_t evFork = nullptr, evJoin = nullptr;
    if (!s2) {
        cudaStreamCreateWithFlags(&s2, cudaStreamNonBlocking);
        cudaEventCreateWithFlags(&evFork, cudaEventDisableTiming);
        cudaEventCreateWithFlags(&evJoin, cudaEventDisableTiming);
    }

    // Fork: CSR build on s2, node1 on the main (capture) stream.
    cudaEventRecord(evFork, 0);
    cudaStreamWaitEvent(s2, evFork, 0);

    k_init   <<<nodeBlocks, TB, 0, s2>>>(ei, N);
    k_hist   <<<edgeBlocks, TB, 0, s2>>>(ei, E);
    k_scanA  <<<NB, TB, 0, s2>>>(N);
    k_scanB  <<<1, 1024, 0, s2>>>(NB);
    k_scanC  <<<NB, TB, 0, s2>>>(N);
    k_scatter<<<edgeBlocks, TB, 0, s2>>>(ei, E);
    cudaEventRecord(evJoin, s2);

    // Layer 1 transform runs concurrently with the CSR build.
    k_node1<<<nodeBlocks, TB>>>(x, ax, W1r, W1o, b1, N);

    // Join: fused layer 2 needs both CSR and t1/a1.
    cudaStreamWaitEvent(0, evJoin, 0);
    k_fused2<<<nodeBlocks, TB>>>(lf, W2r, W2o, b2, N);
    k_fused3<<<nodeBlocks, TB>>>(ax, W3r, W3o, b3, out, N);
    k_agg3<<<((long long)N * 4 + TB - 1) / TB, TB>>>(out, N);
}

// round 12
// speedup vs baseline: 1.6992x; 1.6992x over previous
#include <cuda_runtime.h>

// Problem constants (fixed by the dataset)
#define NN 100000
#define EE 1600000

// Scratch: __device__ globals only, referenced ONLY from device code
// (host-side symbol use binds the ATS-dereferenceable host shadow -> R2 bug).
__device__ int   g_is64;
__device__ int   g_deg[NN];      // per-node in-degree (histogram)
__device__ int   g_off[NN];      // exclusive prefix = CSR row start
__device__ int   g_cur[NN];      // scatter cursor
__device__ int   g_csr[EE];      // src indices grouped by dst
__device__ int   g_bsum[1024];   // scan block sums
__device__ float g_t1[NN * 32];
__device__ float g_a1[NN * 32];
__device__ float g_t2[NN * 48];
__device__ float g_a2[NN * 48];
__device__ float g_t3[NN * 16];

// Packed fp32x2 helpers (Blackwell FFMA2 — exact fp32, 2 FMAs/inst)
__device__ __forceinline__ unsigned long long fma2(
    unsigned long long a, unsigned long long b, unsigned long long c) {
    unsigned long long d;
    asm("fma.rn.f32x2 %0, %1, %2, %3;" : "=l"(d) : "l"(a), "l"(b), "l"(c));
    return d;
}
__device__ __forceinline__ unsigned long long add2(
    unsigned long long a, unsigned long long b) {
    unsigned long long d;
    asm("add.rn.f32x2 %0, %1, %2;" : "=l"(d) : "l"(a), "l"(b));
    return d;
}
__device__ __forceinline__ unsigned long long bcast2(float v) {
    unsigned long long d;
    asm("mov.b64 %0, {%1, %1};" : "=l"(d) : "f"(v));
    return d;
}

// ---------------------------------------------------------------------------
// CSR build (runs on side stream, hidden behind node1)
// ---------------------------------------------------------------------------
__global__ __launch_bounds__(256) void k_init(const void* __restrict__ ei, int N) {
    int i = blockIdx.x * blockDim.x + threadIdx.x;
    if (i < N) g_deg[i] = 0;
    if (i == 0) {
        const long long* p = (const long long*)ei;
        int ok = 1;
        for (int q = 0; q < 64; q++) {
            long long v = p[q];
            if (v < 0 || v >= (long long)N) { ok = 0; break; }
        }
        g_is64 = ok;
    }
}

__global__ __launch_bounds__(256) void k_hist(const void* __restrict__ ei, int E) {
    int i = blockIdx.x * blockDim.x + threadIdx.x;
    if (i >= E) return;
    int d;
    if (g_is64) d = (int)((const long long*)ei)[E + i];
    else        d = ((const int*)ei)[E + i];
    atomicAdd(&g_deg[d], 1);
}

// Pass A: per-1024-chunk sums
__global__ __launch_bounds__(256) void k_scanA(int N) {
    __shared__ int s[256];
    int b = blockIdx.x, t = threadIdx.x;
    int base = b * 1024 + t * 4;
    int sum = 0;
#pragma unroll
    for (int i = 0; i < 4; i++) {
        int idx = base + i;
        if (idx < N) sum += g_deg[idx];
    }
    s[t] = sum;
    __syncthreads();
#pragma unroll
    for (int d = 128; d > 0; d >>= 1) {
        if (t < d) s[t] += s[t + d];
        __syncthreads();
    }
    if (t == 0) g_bsum[b] = s[0];
}

// Pass C (fused with the block-sum scan): every block re-scans the <=128
// chunk sums in smem (cheap), then does its local exclusive scan.
__global__ __launch_bounds__(256) void k_scanC(int N, int NB) {
    __shared__ int sb_[128];
    __shared__ int s[256];
    int b = blockIdx.x, t = threadIdx.x;

    // scan the chunk sums (NB <= 128 here; N=100k -> NB=98)
    if (t < 128) sb_[t] = (t < NB) ? g_bsum[t] : 0;
    __syncthreads();
#pragma unroll
    for (int d = 1; d < 128; d <<= 1) {
        int x = (t >= d && t < 128) ? sb_[t - d] : 0;
        __syncthreads();
        if (t < 128) sb_[t] += x;
        __syncthreads();
    }
    int boff = (b == 0) ? 0 : sb_[b - 1];

    int base = b * 1024 + t * 4;
    int v[4];
    int sum = 0;
#pragma unroll
    for (int i = 0; i < 4; i++) {
        int idx = base + i;
        v[i] = (idx < N) ? g_deg[idx] : 0;
        sum += v[i];
    }
    s[t] = sum;
    __syncthreads();
    for (int d = 1; d < 256; d <<= 1) {
        int x = (t >= d) ? s[t - d] : 0;
        __syncthreads();
        s[t] += x;
        __syncthreads();
    }
    int run = s[t] - sum + boff;
#pragma unroll
    for (int i = 0; i < 4; i++) {
        int idx = base + i;
        if (idx < N) {
            g_off[idx] = run;
            g_cur[idx] = run;
            run += v[i];
        }
    }
}

__global__ __launch_bounds__(256) void k_scatter(const void* __restrict__ ei, int E) {
    int i = blockIdx.x * blockDim.x + threadIdx.x;
    if (i >= E) return;
    int s, d;
    if (g_is64) {
        const long long* p = (const long long*)ei;
        s = (int)p[i];
        d = (int)p[E + i];
    } else {
        const int* p = (const int*)ei;
        s = p[i];
        d = p[E + i];
    }
    int pos = atomicAdd(&g_cur[d], 1);
    g_csr[pos] = s;
}

// ---------------------------------------------------------------------------
// Dual-GEMM j-tile body, FFMA2: 8 outputs as 4 packed f32x2 accums per matrix.
// ---------------------------------------------------------------------------
#define JTILE_BODY2(IN, OUT)                                                   \
    unsigned long long at2[4], ar2[4];                                         \
    {                                                                          \
        ulonglong2 binit0 = *(const ulonglong2*)&sb[jt];                       \
        ulonglong2 binit1 = *(const ulonglong2*)&sb[jt + 4];                   \
        at2[0] = 0ull; at2[1] = 0ull; at2[2] = 0ull; at2[3] = 0ull;            \
        ar2[0] = binit0.x; ar2[1] = binit0.y;                                  \
        ar2[2] = binit1.x; ar2[3] = binit1.y;                                  \
    }                                                                          \
    _Pragma("unroll")                                                          \
    for (int k = 0; k < IN; k++) {                                             \
        unsigned long long hk2 = bcast2(h[k]);                                 \
        ulonglong2 wr01 = *(const ulonglong2*)&sWr[k * OUT + jt];              \
        ulonglong2 wr23 = *(const ulonglong2*)&sWr[k * OUT + jt + 4];          \
        ulonglong2 wo01 = *(const ulonglong2*)&sWo[k * OUT + jt];              \
        ulonglong2 wo23 = *(const ulonglong2*)&sWo[k * OUT + jt + 4];          \
        at2[0] = fma2(hk2, wr01.x, at2[0]);                                    \
        at2[1] = fma2(hk2, wr01.y, at2[1]);                                    \
        at2[2] = fma2(hk2, wr23.x, at2[2]);                                    \
        at2[3] = fma2(hk2, wr23.y, at2[3]);                                    \
        ar2[0] = fma2(hk2, wo01.x, ar2[0]);                                    \
        ar2[1] = fma2(hk2, wo01.y, ar2[1]);                                    \
        ar2[2] = fma2(hk2, wo23.x, ar2[2]);                                    \
        ar2[3] = fma2(hk2, wo23.y, ar2[3]);                                    \
    }

// K1: layer 1 node kernel. h0 = concat(x[48], ax[16]) -> 64
__global__ __launch_bounds__(256) void k_node1(
    const float* __restrict__ x, const float* __restrict__ ax,
    const float* __restrict__ Wrel, const float* __restrict__ Wroot,
    const float* __restrict__ b, int N)
{
    __shared__ __align__(16) float sWr[64 * 32];
    __shared__ __align__(16) float sWo[64 * 32];
    __shared__ __align__(16) float sb[32];
    for (int t = threadIdx.x; t < 64 * 32; t += 256) { sWr[t] = Wrel[t]; sWo[t] = Wroot[t]; }
    if (threadIdx.x < 32) sb[threadIdx.x] = b[threadIdx.x];
    __syncthreads();

    int i = blockIdx.x * 256 + threadIdx.x;
    if (i >= N) return;

    float h[64];
    const float4* xp = (const float4*)(x + (size_t)i * 48);
#pragma unroll
    for (int q = 0; q < 12; q++) {
        float4 v = xp[q];
        h[4*q] = v.x; h[4*q+1] = v.y; h[4*q+2] = v.z; h[4*q+3] = v.w;
    }
    const float4* ap = (const float4*)(ax + (size_t)i * 16);
#pragma unroll
    for (int q = 0; q < 4; q++) {
        float4 v = ap[q];
        h[48+4*q] = v.x; h[48+4*q+1] = v.y; h[48+4*q+2] = v.z; h[48+4*q+3] = v.w;
    }

    float* t1 = g_t1 + (size_t)i * 32;
    float* a1 = g_a1 + (size_t)i * 32;
#pragma unroll 1
    for (int jt = 0; jt < 32; jt += 8) {
        JTILE_BODY2(64, 32)
        *(ulonglong2*)&t1[jt]     = make_ulonglong2(at2[0], at2[1]);
        *(ulonglong2*)&t1[jt + 4] = make_ulonglong2(at2[2], at2[3]);
        *(ulonglong2*)&a1[jt]     = make_ulonglong2(ar2[0], ar2[1]);
        *(ulonglong2*)&a1[jt + 4] = make_ulonglong2(ar2[2], ar2[3]);
    }
}

// K3: layer 2 node kernel. h1 = concat(relu(a1)[32], lf[16]) -> 48
__global__ __launch_bounds__(256) void k_node2(
    const float* __restrict__ lf,
    const float* __restrict__ Wrel, const float* __restrict__ Wroot,
    const float* __restrict__ b, int N)
{
    __shared__ __align__(16) float sWr[48 * 48];
    __shared__ __align__(16) float sWo[48 * 48];
    __shared__ __align__(16) float sb[48];
    for (int t = threadIdx.x; t < 48 * 48; t += 256) { sWr[t] = Wrel[t]; sWo[t] = Wroot[t]; }
    if (threadIdx.x < 48) sb[threadIdx.x] = b[threadIdx.x];
    __syncthreads();

    int i = blockIdx.x * 256 + threadIdx.x;
    if (i >= N) return;

    float h[48];
    const float4* a1p = (const float4*)(g_a1 + (size_t)i * 32);
#pragma unroll
    for (int q = 0; q < 8; q++) {
        float4 v = a1p[q];
        h[4*q]   = fmaxf(v.x, 0.0f);
        h[4*q+1] = fmaxf(v.y, 0.0f);
        h[4*q+2] = fmaxf(v.z, 0.0f);
        h[4*q+3] = fmaxf(v.w, 0.0f);
    }
    const float4* lp = (const float4*)(lf + (size_t)i * 16);
#pragma unroll
    for (int q = 0; q < 4; q++) {
        float4 v = lp[q];
        h[32+4*q] = v.x; h[32+4*q+1] = v.y; h[32+4*q+2] = v.z; h[32+4*q+3] = v.w;
    }

    float* t2 = g_t2 + (size_t)i * 48;
    float* a2 = g_a2 + (size_t)i * 48;
#pragma unroll 1
    for (int jt = 0; jt < 48; jt += 8) {
        JTILE_BODY2(48, 48)
        *(ulonglong2*)&t2[jt]     = make_ulonglong2(at2[0], at2[1]);
        *(ulonglong2*)&t2[jt + 4] = make_ulonglong2(at2[2], at2[3]);
        *(ulonglong2*)&a2[jt]     = make_ulonglong2(ar2[0], ar2[1]);
        *(ulonglong2*)&a2[jt + 4] = make_ulonglong2(ar2[2], ar2[3]);
    }
}

// K5: layer 3 node kernel. h2 = relu(a2)[48]; out = h2 @ W3_root + b3 + ax
__global__ __launch_bounds__(256) void k_node3(
    const float* __restrict__ ax,
    const float* __restrict__ Wrel, const float* __restrict__ Wroot,
    const float* __restrict__ b, float* __restrict__ out, int N)
{
    __shared__ __align__(16) float sWr[48 * 16];
    __shared__ __align__(16) float sWo[48 * 16];
    __shared__ __align__(16) float sb[16];
    for (int t = threadIdx.x; t < 48 * 16; t += 256) { sWr[t] = Wrel[t]; sWo[t] = Wroot[t]; }
    if (threadIdx.x < 16) sb[threadIdx.x] = b[threadIdx.x];
    __syncthreads();

    int i = blockIdx.x * 256 + threadIdx.x;
    if (i >= N) return;

    float h[48];
    const float4* a2p = (const float4*)(g_a2 + (size_t)i * 48);
#pragma unroll
    for (int q = 0; q < 12; q++) {
        float4 v = a2p[q];
        h[4*q]   = fmaxf(v.x, 0.0f);
        h[4*q+1] = fmaxf(v.y, 0.0f);
        h[4*q+2] = fmaxf(v.z, 0.0f);
        h[4*q+3] = fmaxf(v.w, 0.0f);
    }

    const ulonglong2* axp = (const ulonglong2*)(ax + (size_t)i * 16);
    float* t3 = g_t3 + (size_t)i * 16;
    float* o  = out + (size_t)i * 16;
#pragma unroll 1
    for (int jt = 0; jt < 16; jt += 8) {
        JTILE_BODY2(48, 16)
        ulonglong2 av0 = axp[jt / 4];
        ulonglong2 av1 = axp[jt / 4 + 1];
        *(ulonglong2*)&t3[jt]     = make_ulonglong2(at2[0], at2[1]);
        *(ulonglong2*)&t3[jt + 4] = make_ulonglong2(at2[2], at2[3]);
        *(ulonglong2*)&o[jt]      = make_ulonglong2(add2(ar2[0], av0.x),
                                                    add2(ar2[1], av0.y));
        *(ulonglong2*)&o[jt + 4]  = make_ulonglong2(add2(ar2[2], av1.x),
                                                    add2(ar2[3], av1.y));
    }
}

// ---------------------------------------------------------------------------
// CSR aggregation: thread (node, chunk) — CH adjacent lanes cover one node's
// row chunks, so each neighbor row is a coalesced 128B line group.
// ---------------------------------------------------------------------------
template <int CH>
__device__ __forceinline__ void agg_body(
    const float* __restrict__ t, float* __restrict__ acc, int N)
{
    int tid = blockIdx.x * blockDim.x + threadIdx.x;
    if (tid >= N * CH) return;
    int n = tid / CH;
    int c = tid - n * CH;

    int beg = g_off[n];
    int end = beg + g_deg[n];

    float4 a = make_float4(0.f, 0.f, 0.f, 0.f);
    float4 a2 = make_float4(0.f, 0.f, 0.f, 0.f);

    int j = beg;
    for (; j + 3 < end; j += 4) {
        int s0 = g_csr[j], s1 = g_csr[j+1], s2 = g_csr[j+2], s3 = g_csr[j+3];
        float4 v0 = *(const float4*)(t + (size_t)s0 * (CH*4) + c*4);
        float4 v1 = *(const float4*)(t + (size_t)s1 * (CH*4) + c*4);
        float4 v2 = *(const float4*)(t + (size_t)s2 * (CH*4) + c*4);
        float4 v3 = *(const float4*)(t + (size_t)s3 * (CH*4) + c*4);
        a.x += v0.x; a.y += v0.y; a.z += v0.z; a.w += v0.w;
        a2.x += v1.x; a2.y += v1.y; a2.z += v1.z; a2.w += v1.w;
        a.x += v2.x; a.y += v2.y; a.z += v2.z; a.w += v2.w;
        a2.x += v3.x; a2.y += v3.y; a2.z += v3.z; a2.w += v3.w;
    }
    for (; j < end; j++) {
        int s = g_csr[j];
        float4 v = *(const float4*)(t + (size_t)s * (CH*4) + c*4);
        a.x += v.x; a.y += v.y; a.z += v.z; a.w += v.w;
    }

    float* ap = acc + (size_t)n * (CH*4) + c*4;
    float4 cur = *(float4*)ap;
    *(float4*)ap = make_float4(cur.x + a.x + a2.x, cur.y + a.y + a2.y,
                               cur.z + a.z + a2.z, cur.w + a.w + a2.w);
}

__global__ __launch_bounds__(256) void k_agg1(int N) { agg_body<8> (g_t1, g_a1, N); }
__global__ __launch_bounds__(256) void k_agg2(int N) { agg_body<12>(g_t2, g_a2, N); }
__global__ __launch_bounds__(256) void k_agg3(float* __restrict__ out, int N) {
    agg_body<4>(g_t3, out, N);
}

// ---------------------------------------------------------------------------
// kernel_launch: CSR build on side stream overlapped with k_node1.
// ---------------------------------------------------------------------------
extern "C" void kernel_launch(void* const* d_in, const int* in_sizes, int n_in,
                              void* d_out, int out_size)
{
    const float* x   = (const float*)d_in[0];
    const void*  ei  = d_in[1];
    const float* ax  = (const float*)d_in[2];
    const float* lf  = (const float*)d_in[3];
    const float* W1r = (const float*)d_in[4];
    const float* b1  = (const float*)d_in[5];
    const float* W1o = (const float*)d_in[6];
    const float* W2r = (const float*)d_in[7];
    const float* b2  = (const float*)d_in[8];
    const float* W2o = (const float*)d_in[9];
    const float* W3r = (const float*)d_in[10];
    const float* b3  = (const float*)d_in[11];
    const float* W3o = (const float*)d_in[12];
    float* out = (float*)d_out;

    const int N = in_sizes[0] / 48;
    const int E = in_sizes[1] / 2;

    const int TB = 256;
    const int nodeBlocks = (N + TB - 1) / TB;
    const int edgeBlocks = (E + TB - 1) / TB;
    const int NB = (N + 1023) / 1024;   // scan blocks (98 for N=100k, <=128)

    static cudaStream_t s2 = nullptr;
    static cudaEvent_t evFork = nullptr, evJoin = nullptr;
    if (!s2) {
        cudaStreamCreateWithFlags(&s2, cudaStreamNonBlocking);
        cudaEventCreateWithFlags(&evFork, cudaEventDisableTiming);
        cudaEventCreateWithFlags(&evJoin, cudaEventDisableTiming);
    }

    // Fork: CSR build on s2, node1 on the main (capture) stream.
    cudaEventRecord(evFork, 0);
    cudaStreamWaitEvent(s2, evFork, 0);

    k_init   <<<nodeBlocks, TB, 0, s2>>>(ei, N);
    k_hist   <<<edgeBlocks, TB, 0, s2>>>(ei, E);
    k_scanA  <<<NB, TB, 0, s2>>>(N);
    k_scanC  <<<NB, TB, 0, s2>>>(N, NB);
    k_scatter<<<edgeBlocks, TB, 0, s2>>>(ei, E);
    cudaEventRecord(evJoin, s2);

    // Layer 1 transform runs concurrently with the CSR build.
    k_node1<<<nodeBlocks, TB>>>(x, ax, W1r, W1o, b1, N);

    // Join: aggregation needs both CSR and t1.
    cudaStreamWaitEvent(0, evJoin, 0);
    k_agg1<<<((long long)N * 8 + TB - 1) / TB, TB>>>(N);

    // Layer 2 (width 48 -> CH=12)
    k_node2<<<nodeBlocks, TB>>>(lf, W2r, W2o, b2, N);
    k_agg2<<<((long long)N * 12 + TB - 1) / TB, TB>>>(N);

    // Layer 3 (width 16 -> CH=4), accumulate straight into d_out
    k_node3<<<nodeBlocks, TB>>>(ax, W3r, W3o, b3, out, N);
    k_agg3<<<((long long)N * 4 + TB - 1) / TB, TB>>>(out, N);
}